// round 1
// baseline (speedup 1.0000x reference)
#include <cuda_runtime.h>
#include <cstdint>

#define B_ 8
#define N_ 200
#define D_ 128
#define BN_ (B_ * N_)            // 1600
#define HSZ (B_ * N_ * D_)       // 204800
#define ESZ (B_ * N_ * N_ * D_)  // 40960000
#define EPS 1e-5f

// ---------------- scratch (device globals, no allocation) ----------------
__device__ float g_Uh[HSZ];
__device__ float g_Vh[HSZ];
__device__ float g_Ah[HSZ];
__device__ float g_Bh[HSZ];
__device__ float g_hnew[HSZ];
__device__ float g_acc[4 * D_];   // e_sum, e_sqsum, h_sum, h_sqsum
__device__ float g_coef[4 * D_];  // scale_e, shift_e, scale_h, shift_h

// ---------------- K0: zero accumulators (must run every launch) ----------
__global__ void zero_acc_kernel() {
    int t = threadIdx.x;
    if (t < 4 * D_) g_acc[t] = 0.0f;
}

// ---------------- K1: four projections  Xh = h @ Xw^T + Xb ----------------
// grid 200 blocks x 128 threads; each block handles 8 rows of h.
// dynamic smem: hs[8][128] + wt[128][129]
__global__ void proj_kernel(const float* __restrict__ h,
                            const float* __restrict__ Uw, const float* __restrict__ Ub,
                            const float* __restrict__ Vw, const float* __restrict__ Vb,
                            const float* __restrict__ Aw, const float* __restrict__ Ab,
                            const float* __restrict__ Bw, const float* __restrict__ Bb) {
    extern __shared__ float sm[];
    float* hs = sm;              // 8*128 = 1024 floats
    float* wt = sm + 1024;       // 128*129 = 16512 floats
    const int tid = threadIdx.x;   // 0..127
    const int row0 = blockIdx.x * 8;

#pragma unroll
    for (int r = 0; r < 8; r++) hs[r * D_ + tid] = h[(row0 + r) * D_ + tid];

    const float* Ws[4] = {Uw, Vw, Aw, Bw};
    const float* bs[4] = {Ub, Vb, Ab, Bb};
    float* outs[4] = {g_Uh, g_Vh, g_Ah, g_Bh};

    for (int m = 0; m < 4; m++) {
        __syncthreads();
        // load W transposed into wt[k][d] (padded stride 129)
        const float4* W4 = reinterpret_cast<const float4*>(Ws[m]);
#pragma unroll
        for (int t = 0; t < 32; t++) {
            int idx4 = t * 128 + tid;       // 0..4095
            float4 v = W4[idx4];
            int d = idx4 >> 5;              // idx4*4 / 128
            int k = (idx4 & 31) << 2;
            wt[(k + 0) * 129 + d] = v.x;
            wt[(k + 1) * 129 + d] = v.y;
            wt[(k + 2) * 129 + d] = v.z;
            wt[(k + 3) * 129 + d] = v.w;
        }
        __syncthreads();

        float acc[8] = {0, 0, 0, 0, 0, 0, 0, 0};
        for (int k = 0; k < D_; k++) {
            float w = wt[k * 129 + tid];
#pragma unroll
            for (int r = 0; r < 8; r++) acc[r] += hs[r * D_ + k] * w;
        }
        float bias = bs[m][tid];
#pragma unroll
        for (int r = 0; r < 8; r++)
            outs[m][(row0 + r) * D_ + tid] = acc[r] + bias;
    }
}

// ---------------- K2: fused  Ce GEMM + e_new + gates + agg + stats --------
// grid = 1600 blocks (one per (b,i)), 128 threads (4 warps).
// warp w owns j-subset {j0 + 5w .. j0 + 5w + 4}; lane owns d = lane + 32q, q=0..3.
// dynamic smem: cwt[128][129] (16512) + es[20][128] (2560) + red[3][128] (384)
__global__ void __launch_bounds__(128) fuse_kernel(const float* __restrict__ e,
                                                   const float* __restrict__ Cw,
                                                   const float* __restrict__ Cb,
                                                   float* __restrict__ e_new_out) {
    extern __shared__ float sm[];
    float* cwt = sm;               // [k*129 + d]
    float* es = sm + 16512;        // [jj*128 + k]
    float* red = sm + 16512 + 2560; // [0]=agg [1]=sum [2]=sq, each 128

    const int tid = threadIdx.x;
    const int lane = tid & 31;
    const int warp = tid >> 5;
    const int bi = blockIdx.x;
    const int b = bi / N_;
    const int i = bi - b * N_;

    // load Cw transposed
    {
        const float4* C4 = reinterpret_cast<const float4*>(Cw);
#pragma unroll
        for (int t = 0; t < 32; t++) {
            int idx4 = t * 128 + tid;
            float4 v = C4[idx4];
            int d = idx4 >> 5;
            int k = (idx4 & 31) << 2;
            cwt[(k + 0) * 129 + d] = v.x;
            cwt[(k + 1) * 129 + d] = v.y;
            cwt[(k + 2) * 129 + d] = v.z;
            cwt[(k + 3) * 129 + d] = v.w;
        }
    }
    red[0 * D_ + tid] = 0.0f;
    red[1 * D_ + tid] = 0.0f;
    red[2 * D_ + tid] = 0.0f;

    const float* e_base = e + (size_t)bi * N_ * D_;
    const float* Ah_b = g_Ah + b * N_ * D_;
    const float* Vh_b = g_Vh + b * N_ * D_;

    float Bh_r[4], Cb_r[4];
#pragma unroll
    for (int q = 0; q < 4; q++) {
        int d = lane + 32 * q;
        Bh_r[q] = g_Bh[(size_t)bi * D_ + d];
        Cb_r[q] = Cb[d];
    }

    float aggp[4] = {0, 0, 0, 0};
    float sump[4] = {0, 0, 0, 0};
    float sqp[4] = {0, 0, 0, 0};

    for (int j0 = 0; j0 < N_; j0 += 20) {
        __syncthreads();
        // stage 20 e rows (2560 floats = 640 float4)
        const float4* er = reinterpret_cast<const float4*>(e_base + (size_t)j0 * D_);
        float4* es4 = reinterpret_cast<float4*>(es);
#pragma unroll
        for (int t = 0; t < 5; t++) es4[t * 128 + tid] = er[t * 128 + tid];
        __syncthreads();

        float acc[5][4];
#pragma unroll
        for (int u = 0; u < 5; u++)
#pragma unroll
            for (int q = 0; q < 4; q++) acc[u][q] = 0.0f;

        for (int k4 = 0; k4 < 32; k4++) {
            const int k = k4 * 4;
            float c0[4], c1[4], c2[4], c3[4];
#pragma unroll
            for (int q = 0; q < 4; q++) {
                int d = lane + 32 * q;
                c0[q] = cwt[(k + 0) * 129 + d];
                c1[q] = cwt[(k + 1) * 129 + d];
                c2[q] = cwt[(k + 2) * 129 + d];
                c3[q] = cwt[(k + 3) * 129 + d];
            }
#pragma unroll
            for (int u = 0; u < 5; u++) {
                float4 ev = *reinterpret_cast<const float4*>(&es[(warp * 5 + u) * D_ + k]);
#pragma unroll
                for (int q = 0; q < 4; q++) {
                    acc[u][q] += ev.x * c0[q];
                    acc[u][q] += ev.y * c1[q];
                    acc[u][q] += ev.z * c2[q];
                    acc[u][q] += ev.w * c3[q];
                }
            }
        }

        // epilogue for this tile
#pragma unroll
        for (int u = 0; u < 5; u++) {
            const int j = j0 + warp * 5 + u;
#pragma unroll
            for (int q = 0; q < 4; q++) {
                const int d = lane + 32 * q;
                float x = acc[u][q] + Cb_r[q] + Bh_r[q] + Ah_b[j * D_ + d];
                e_new_out[((size_t)bi * N_ + j) * D_ + d] = x;
                sump[q] += x;
                sqp[q] += x * x;
                float gte = __fdividef(1.0f, 1.0f + __expf(-x));
                aggp[q] += gte * Vh_b[j * D_ + d];
            }
        }
    }

    // cross-warp reduction (warps cover disjoint j's, same d's)
#pragma unroll
    for (int q = 0; q < 4; q++) {
        int d = lane + 32 * q;
        atomicAdd(&red[0 * D_ + d], aggp[q]);
        atomicAdd(&red[1 * D_ + d], sump[q]);
        atomicAdd(&red[2 * D_ + d], sqp[q]);
    }
    __syncthreads();

    {
        const int d = tid;
        float hn = g_Uh[(size_t)bi * D_ + d] + red[0 * D_ + d];
        g_hnew[(size_t)bi * D_ + d] = hn;
        atomicAdd(&g_acc[0 * D_ + d], red[1 * D_ + d]);
        atomicAdd(&g_acc[1 * D_ + d], red[2 * D_ + d]);
        atomicAdd(&g_acc[2 * D_ + d], hn);
        atomicAdd(&g_acc[3 * D_ + d], hn * hn);
    }
}

// ---------------- K3: BN stats -> scale/shift -----------------------------
__global__ void finalize_stats_kernel(const float* __restrict__ gamma_e,
                                      const float* __restrict__ beta_e,
                                      const float* __restrict__ gamma_h,
                                      const float* __restrict__ beta_h) {
    int d = threadIdx.x;  // 128
    const float Ne = (float)B_ * N_ * N_;
    float mu = g_acc[d] / Ne;
    float var = g_acc[D_ + d] / Ne - mu * mu;
    float sc = rsqrtf(var + EPS) * gamma_e[d];
    g_coef[d] = sc;
    g_coef[D_ + d] = beta_e[d] - mu * sc;

    const float Nh = (float)B_ * N_;
    float muh = g_acc[2 * D_ + d] / Nh;
    float varh = g_acc[3 * D_ + d] / Nh - muh * muh;
    float sch = rsqrtf(varh + EPS) * gamma_h[d];
    g_coef[2 * D_ + d] = sch;
    g_coef[3 * D_ + d] = beta_h[d] - muh * sch;
}

// ---------------- K4: e epilogue (in-place over e_new region) -------------
__global__ void efinal_kernel(const float* __restrict__ e_in, float* __restrict__ e_out) {
    size_t idx = (size_t)blockIdx.x * blockDim.x + threadIdx.x;  // float4 index
    int d4 = (int)(idx & 31);
    float4 sc = reinterpret_cast<const float4*>(g_coef)[d4];
    float4 sh = reinterpret_cast<const float4*>(g_coef + D_)[d4];
    float4 x = reinterpret_cast<const float4*>(e_out)[idx];
    float4 ei = reinterpret_cast<const float4*>(e_in)[idx];
    float4 r;
    r.x = ei.x + fmaxf(0.0f, x.x * sc.x + sh.x);
    r.y = ei.y + fmaxf(0.0f, x.y * sc.y + sh.y);
    r.z = ei.z + fmaxf(0.0f, x.z * sc.z + sh.z);
    r.w = ei.w + fmaxf(0.0f, x.w * sc.w + sh.w);
    reinterpret_cast<float4*>(e_out)[idx] = r;
}

// ---------------- K5: h epilogue ------------------------------------------
__global__ void hfinal_kernel(const float* __restrict__ h_in, float* __restrict__ h_out) {
    size_t idx = (size_t)blockIdx.x * blockDim.x + threadIdx.x;  // float4 index
    int d4 = (int)(idx & 31);
    float4 sc = reinterpret_cast<const float4*>(g_coef + 2 * D_)[d4];
    float4 sh = reinterpret_cast<const float4*>(g_coef + 3 * D_)[d4];
    float4 x = reinterpret_cast<const float4*>(g_hnew)[idx];
    float4 hi = reinterpret_cast<const float4*>(h_in)[idx];
    float4 r;
    r.x = hi.x + fmaxf(0.0f, x.x * sc.x + sh.x);
    r.y = hi.y + fmaxf(0.0f, x.y * sc.y + sh.y);
    r.z = hi.z + fmaxf(0.0f, x.z * sc.z + sh.z);
    r.w = hi.w + fmaxf(0.0f, x.w * sc.w + sh.w);
    reinterpret_cast<float4*>(h_out)[idx] = r;
}

// ---------------- launch ---------------------------------------------------
extern "C" void kernel_launch(void* const* d_in, const int* in_sizes, int n_in,
                              void* d_out, int out_size) {
    const float* h = (const float*)d_in[0];
    const float* e = (const float*)d_in[1];
    const float* Uw = (const float*)d_in[2];
    const float* Ub = (const float*)d_in[3];
    const float* Vw = (const float*)d_in[4];
    const float* Vb = (const float*)d_in[5];
    const float* Aw = (const float*)d_in[6];
    const float* Ab = (const float*)d_in[7];
    const float* Bw = (const float*)d_in[8];
    const float* Bb = (const float*)d_in[9];
    const float* Cw = (const float*)d_in[10];
    const float* Cb = (const float*)d_in[11];
    const float* gamma_h = (const float*)d_in[12];
    const float* beta_h = (const float*)d_in[13];
    const float* gamma_e = (const float*)d_in[14];
    const float* beta_e = (const float*)d_in[15];

    float* out = (float*)d_out;
    float* h_out = out;          // [B,N,D]
    float* e_out = out + HSZ;    // [B,N,N,D] (also used as e_new scratch)

    static int attr_done = 0;
    const int proj_smem = (1024 + 16512) * 4;            // 70144 B
    const int fuse_smem = (16512 + 2560 + 3 * 128) * 4;  // 77824 B
    if (!attr_done) {
        cudaFuncSetAttribute(proj_kernel, cudaFuncAttributeMaxDynamicSharedMemorySize, proj_smem);
        cudaFuncSetAttribute(fuse_kernel, cudaFuncAttributeMaxDynamicSharedMemorySize, fuse_smem);
        attr_done = 1;
    }

    zero_acc_kernel<<<1, 512>>>();
    proj_kernel<<<BN_ / 8, 128, proj_smem>>>(h, Uw, Ub, Vw, Vb, Aw, Ab, Bw, Bb);
    fuse_kernel<<<BN_, 128, fuse_smem>>>(e, Cw, Cb, e_out);
    finalize_stats_kernel<<<1, 128>>>(gamma_e, beta_e, gamma_h, beta_h);
    efinal_kernel<<<ESZ / 4 / 256, 256>>>(e, e_out);
    hfinal_kernel<<<HSZ / 4 / 256, 256>>>(h, h_out);
}

// round 3
// speedup vs baseline: 1.2967x; 1.2967x over previous
#include <cuda_runtime.h>
#include <cuda_bf16.h>
#include <cstdint>

#define B_ 8
#define N_ 200
#define D_ 128
#define BN_ (B_ * N_)            // 1600
#define HSZ (B_ * N_ * D_)       // 204800
#define ESZ (B_ * N_ * N_ * D_)  // 40960000
#define EPS 1e-5f

// ---------------- scratch (device globals, no allocation) ----------------
__device__ float g_Uh[HSZ];
__device__ float g_Vh[HSZ];
__device__ float g_Ah[HSZ];
__device__ float g_Bh[HSZ];
__device__ float g_hnew[HSZ];
__device__ float g_acc[4 * D_];   // e_sum, e_sqsum, h_sum, h_sqsum
__device__ float g_coef[4 * D_];  // scale_e, shift_e, scale_h, shift_h

// ---------------- K0: zero accumulators ----------------
__global__ void zero_acc_kernel() {
    int t = threadIdx.x;
    if (t < 4 * D_) g_acc[t] = 0.0f;
}

// ---------------- K1: four projections  Xh = h @ Xw^T + Xb ----------------
__global__ void proj_kernel(const float* __restrict__ h,
                            const float* __restrict__ Uw, const float* __restrict__ Ub,
                            const float* __restrict__ Vw, const float* __restrict__ Vb,
                            const float* __restrict__ Aw, const float* __restrict__ Ab,
                            const float* __restrict__ Bw, const float* __restrict__ Bb) {
    extern __shared__ float sm[];
    float* hs = sm;              // 8*128
    float* wt = sm + 1024;       // 128*129
    const int tid = threadIdx.x;
    const int row0 = blockIdx.x * 8;

#pragma unroll
    for (int r = 0; r < 8; r++) hs[r * D_ + tid] = h[(row0 + r) * D_ + tid];

    const float* Ws[4] = {Uw, Vw, Aw, Bw};
    const float* bs[4] = {Ub, Vb, Ab, Bb};
    float* outs[4] = {g_Uh, g_Vh, g_Ah, g_Bh};

    for (int m = 0; m < 4; m++) {
        __syncthreads();
        const float4* W4 = reinterpret_cast<const float4*>(Ws[m]);
#pragma unroll
        for (int t = 0; t < 32; t++) {
            int idx4 = t * 128 + tid;
            float4 v = W4[idx4];
            int d = idx4 >> 5;
            int k = (idx4 & 31) << 2;
            wt[(k + 0) * 129 + d] = v.x;
            wt[(k + 1) * 129 + d] = v.y;
            wt[(k + 2) * 129 + d] = v.z;
            wt[(k + 3) * 129 + d] = v.w;
        }
        __syncthreads();

        float acc[8] = {0, 0, 0, 0, 0, 0, 0, 0};
        for (int k = 0; k < D_; k++) {
            float w = wt[k * 129 + tid];
#pragma unroll
            for (int r = 0; r < 8; r++) acc[r] += hs[r * D_ + k] * w;
        }
        float bias = bs[m][tid];
#pragma unroll
        for (int r = 0; r < 8; r++)
            outs[m][(row0 + r) * D_ + tid] = acc[r] + bias;
    }
}

// ================= bf16 helpers ===========================================
__device__ __forceinline__ uint32_t pack_bf(float x, float y) {
    __nv_bfloat162 p = __floats2bfloat162_rn(x, y);
    return *reinterpret_cast<uint32_t*>(&p);
}

__device__ __forceinline__ void mma16816(float* c,
                                         uint32_t a0, uint32_t a1, uint32_t a2, uint32_t a3,
                                         uint32_t b0, uint32_t b1) {
    asm volatile(
        "mma.sync.aligned.m16n8k16.row.col.f32.bf16.bf16.f32 "
        "{%0,%1,%2,%3}, {%4,%5,%6,%7}, {%8,%9}, {%0,%1,%2,%3};"
        : "+f"(c[0]), "+f"(c[1]), "+f"(c[2]), "+f"(c[3])
        : "r"(a0), "r"(a1), "r"(a2), "r"(a3), "r"(b0), "r"(b1));
}

// smem word-layout constants
#define CW_STRIDE 136   // words per k2-row of Cw tiles (128 + 8 pad)
#define E_STRIDE 68     // words per j-row of e tiles (64 + 4 pad)
#define XS_STRIDE 132   // floats per j-row of x tile (128 + 4 pad)
#define CW_WORDS (64 * CW_STRIDE)       // 8704 words per tile
#define E_WORDS (64 * E_STRIDE)         // 4352 words per tile

// ---------------- K2: mma.sync fused  Ce + e_new + gates + agg + stats ----
// grid = 1600 blocks (one per (b,i)), 128 threads (4 warps).
// D[j,d] = sum_k e[bi,j,k] * Cw[d,k] via bf16x3 split (HH + HL + LH).
// smem(words): cw_hi[64][136], cw_lo[64][136], e_hi[64][68], e_lo[64][68]
//              XS float[64][132] overlays the e area after mma.
__global__ void __launch_bounds__(128, 1)
fuse_mma_kernel(const float* __restrict__ e,
                const float* __restrict__ Cw,
                const float* __restrict__ Cb,
                float* __restrict__ e_new_out) {
    extern __shared__ uint32_t smw[];
    uint32_t* cw_hi = smw;
    uint32_t* cw_lo = smw + CW_WORDS;
    uint32_t* e_hi = smw + 2 * CW_WORDS;
    uint32_t* e_lo = smw + 2 * CW_WORDS + E_WORDS;
    float* XS = reinterpret_cast<float*>(smw + 2 * CW_WORDS);  // overlays e tiles

    const int tid = threadIdx.x;
    const int lane = tid & 31;
    const int warp = tid >> 5;
    const int g = lane >> 2;       // groupID
    const int tig = lane & 3;      // thread-in-group
    const int bi = blockIdx.x;
    const int b = bi / N_;

    // ---- stage Cw (transpose + bf16 hi/lo pair-pack), once per block ----
    // thread owns d = tid; loop k4 = 0..31
    {
        const float4* C4 = reinterpret_cast<const float4*>(Cw);
#pragma unroll 4
        for (int t = 0; t < 32; t++) {
            float4 v = C4[tid * 32 + t];
            float hx = __bfloat162float(__float2bfloat16(v.x));
            float hy = __bfloat162float(__float2bfloat16(v.y));
            float hz = __bfloat162float(__float2bfloat16(v.z));
            float hw = __bfloat162float(__float2bfloat16(v.w));
            cw_hi[(2 * t + 0) * CW_STRIDE + tid] = pack_bf(hx, hy);
            cw_hi[(2 * t + 1) * CW_STRIDE + tid] = pack_bf(hz, hw);
            cw_lo[(2 * t + 0) * CW_STRIDE + tid] = pack_bf(v.x - hx, v.y - hy);
            cw_lo[(2 * t + 1) * CW_STRIDE + tid] = pack_bf(v.z - hz, v.w - hw);
        }
    }

    const float* e_base = e + (size_t)bi * N_ * D_;
    float* eo_base = e_new_out + (size_t)bi * N_ * D_;
    const float* Ah_b = g_Ah + (size_t)b * N_ * D_;
    const float* Vh_b = g_Vh + (size_t)b * N_ * D_;
    const float Bh_r = g_Bh[(size_t)bi * D_ + tid];
    const float Cb_r = Cb[tid];

    float sumv = 0.0f, sqv = 0.0f, aggv = 0.0f;

    for (int tile = 0; tile < 4; tile++) {
        const int j0 = tile * 64;
        const int jcnt = (tile < 3) ? 64 : (N_ - 192);   // 64,64,64,8
        const int mtiles = (jcnt + 15) >> 4;             // 4,4,4,1

        __syncthreads();
        // ---- stage e rows [j0, j0+jcnt) as bf16 hi/lo pairs ----
        {
            const float4* E4 = reinterpret_cast<const float4*>(e_base + (size_t)j0 * D_);
            const int nf4 = jcnt * 32;
            for (int fid = tid; fid < nf4; fid += 128) {
                int row = fid >> 5;
                int k4 = fid & 31;
                float4 v = E4[fid];
                float hx = __bfloat162float(__float2bfloat16(v.x));
                float hy = __bfloat162float(__float2bfloat16(v.y));
                float hz = __bfloat162float(__float2bfloat16(v.z));
                float hw = __bfloat162float(__float2bfloat16(v.w));
                int wofs = row * E_STRIDE + 2 * k4;
                e_hi[wofs + 0] = pack_bf(hx, hy);
                e_hi[wofs + 1] = pack_bf(hz, hw);
                e_lo[wofs + 0] = pack_bf(v.x - hx, v.y - hy);
                e_lo[wofs + 1] = pack_bf(v.z - hz, v.w - hw);
            }
            // zero-fill rows jcnt .. mtiles*16 for the partial tile
            if (jcnt < 64) {
                const int zrows = mtiles * 16 - jcnt;    // 8
                const int nzw = zrows * E_STRIDE;
                for (int wz = tid; wz < nzw; wz += 128) {
                    e_hi[jcnt * E_STRIDE + wz] = 0u;
                    e_lo[jcnt * E_STRIDE + wz] = 0u;
                }
            }
        }
        __syncthreads();

        // ---- mma: warp w handles j rows [16w, 16w+16) ----
        float acc[16][4];
        if (warp < mtiles) {
#pragma unroll
            for (int nt = 0; nt < 16; nt++)
#pragma unroll
                for (int q = 0; q < 4; q++) acc[nt][q] = 0.0f;

#pragma unroll
            for (int p = 0; p < 3; p++) {
                const uint32_t* A = (p == 2 ? e_lo : e_hi) + warp * 16 * E_STRIDE;
                const uint32_t* Bm = (p == 1 ? cw_lo : cw_hi);
#pragma unroll
                for (int ks = 0; ks < 8; ks++) {
                    uint32_t a0 = A[g * E_STRIDE + 8 * ks + tig];
                    uint32_t a1 = A[(g + 8) * E_STRIDE + 8 * ks + tig];
                    uint32_t a2 = A[g * E_STRIDE + 8 * ks + tig + 4];
                    uint32_t a3 = A[(g + 8) * E_STRIDE + 8 * ks + tig + 4];
                    const uint32_t* Brow0 = Bm + (8 * ks + tig) * CW_STRIDE + g;
                    const uint32_t* Brow1 = Bm + (8 * ks + tig + 4) * CW_STRIDE + g;
#pragma unroll
                    for (int nt = 0; nt < 16; nt++) {
                        uint32_t b0 = Brow0[8 * nt];
                        uint32_t b1 = Brow1[8 * nt];
                        mma16816(acc[nt], a0, a1, a2, a3, b0, b1);
                    }
                }
            }
        }
        __syncthreads();   // everyone done reading e tiles

        // ---- spill raw Ce accumulators to XS (overlays e tiles) ----
        if (warp < mtiles) {
            const int r0 = warp * 16 + g;
#pragma unroll
            for (int nt = 0; nt < 16; nt++) {
                const int c0 = 8 * nt + 2 * tig;
                *reinterpret_cast<float2*>(&XS[r0 * XS_STRIDE + c0]) =
                    make_float2(acc[nt][0], acc[nt][1]);
                *reinterpret_cast<float2*>(&XS[(r0 + 8) * XS_STRIDE + c0]) =
                    make_float2(acc[nt][2], acc[nt][3]);
            }
        }
        __syncthreads();

        // ---- column pass: thread owns channel d = tid ----
        for (int j = 0; j < jcnt; j++) {
            float x = XS[j * XS_STRIDE + tid] + Cb_r + Bh_r + Ah_b[(j0 + j) * D_ + tid];
            eo_base[(size_t)(j0 + j) * D_ + tid] = x;
            sumv += x;
            sqv += x * x;
            float gte = __fdividef(1.0f, 1.0f + __expf(-x));
            aggv += gte * Vh_b[(j0 + j) * D_ + tid];
        }
    }

    // ---- per-block finish: d = tid owns complete reductions ----
    {
        const int d = tid;
        float hn = g_Uh[(size_t)bi * D_ + d] + aggv;
        g_hnew[(size_t)bi * D_ + d] = hn;
        atomicAdd(&g_acc[0 * D_ + d], sumv);
        atomicAdd(&g_acc[1 * D_ + d], sqv);
        atomicAdd(&g_acc[2 * D_ + d], hn);
        atomicAdd(&g_acc[3 * D_ + d], hn * hn);
    }
}

// ---------------- K3: BN stats -> scale/shift -----------------------------
__global__ void finalize_stats_kernel(const float* __restrict__ gamma_e,
                                      const float* __restrict__ beta_e,
                                      const float* __restrict__ gamma_h,
                                      const float* __restrict__ beta_h) {
    int d = threadIdx.x;
    const float Ne = (float)B_ * N_ * N_;
    float mu = g_acc[d] / Ne;
    float var = g_acc[D_ + d] / Ne - mu * mu;
    float sc = rsqrtf(var + EPS) * gamma_e[d];
    g_coef[d] = sc;
    g_coef[D_ + d] = beta_e[d] - mu * sc;

    const float Nh = (float)B_ * N_;
    float muh = g_acc[2 * D_ + d] / Nh;
    float varh = g_acc[3 * D_ + d] / Nh - muh * muh;
    float sch = rsqrtf(varh + EPS) * gamma_h[d];
    g_coef[2 * D_ + d] = sch;
    g_coef[3 * D_ + d] = beta_h[d] - muh * sch;
}

// ---------------- K4: e epilogue (in-place over e_new region) -------------
__global__ void efinal_kernel(const float* __restrict__ e_in, float* __restrict__ e_out) {
    size_t idx = (size_t)blockIdx.x * blockDim.x + threadIdx.x;
    int d4 = (int)(idx & 31);
    float4 sc = reinterpret_cast<const float4*>(g_coef)[d4];
    float4 sh = reinterpret_cast<const float4*>(g_coef + D_)[d4];
    float4 x = reinterpret_cast<const float4*>(e_out)[idx];
    float4 ei = reinterpret_cast<const float4*>(e_in)[idx];
    float4 r;
    r.x = ei.x + fmaxf(0.0f, x.x * sc.x + sh.x);
    r.y = ei.y + fmaxf(0.0f, x.y * sc.y + sh.y);
    r.z = ei.z + fmaxf(0.0f, x.z * sc.z + sh.z);
    r.w = ei.w + fmaxf(0.0f, x.w * sc.w + sh.w);
    reinterpret_cast<float4*>(e_out)[idx] = r;
}

// ---------------- K5: h epilogue ------------------------------------------
__global__ void hfinal_kernel(const float* __restrict__ h_in, float* __restrict__ h_out) {
    size_t idx = (size_t)blockIdx.x * blockDim.x + threadIdx.x;
    int d4 = (int)(idx & 31);
    float4 sc = reinterpret_cast<const float4*>(g_coef + 2 * D_)[d4];
    float4 sh = reinterpret_cast<const float4*>(g_coef + 3 * D_)[d4];
    float4 x = reinterpret_cast<const float4*>(g_hnew)[idx];
    float4 hi = reinterpret_cast<const float4*>(h_in)[idx];
    float4 r;
    r.x = hi.x + fmaxf(0.0f, x.x * sc.x + sh.x);
    r.y = hi.y + fmaxf(0.0f, x.y * sc.y + sh.y);
    r.z = hi.z + fmaxf(0.0f, x.z * sc.z + sh.z);
    r.w = hi.w + fmaxf(0.0f, x.w * sc.w + sh.w);
    reinterpret_cast<float4*>(h_out)[idx] = r;
}

// ---------------- launch ---------------------------------------------------
extern "C" void kernel_launch(void* const* d_in, const int* in_sizes, int n_in,
                              void* d_out, int out_size) {
    const float* h = (const float*)d_in[0];
    const float* e = (const float*)d_in[1];
    const float* Uw = (const float*)d_in[2];
    const float* Ub = (const float*)d_in[3];
    const float* Vw = (const float*)d_in[4];
    const float* Vb = (const float*)d_in[5];
    const float* Aw = (const float*)d_in[6];
    const float* Ab = (const float*)d_in[7];
    const float* Bw = (const float*)d_in[8];
    const float* Bb = (const float*)d_in[9];
    const float* Cw = (const float*)d_in[10];
    const float* Cb = (const float*)d_in[11];
    const float* gamma_h = (const float*)d_in[12];
    const float* beta_h = (const float*)d_in[13];
    const float* gamma_e = (const float*)d_in[14];
    const float* beta_e = (const float*)d_in[15];

    float* out = (float*)d_out;
    float* h_out = out;          // [B,N,D]
    float* e_out = out + HSZ;    // [B,N,N,D] (e_new scratch then final)

    static int attr_done = 0;
    const int proj_smem = (1024 + 16512) * 4;                 // 70144 B
    const int fuse_smem = (2 * CW_WORDS + 2 * E_WORDS) * 4;   // 104448 B
    if (!attr_done) {
        cudaFuncSetAttribute(proj_kernel, cudaFuncAttributeMaxDynamicSharedMemorySize, proj_smem);
        cudaFuncSetAttribute(fuse_mma_kernel, cudaFuncAttributeMaxDynamicSharedMemorySize, fuse_smem);
        attr_done = 1;
    }

    zero_acc_kernel<<<1, 512>>>();
    proj_kernel<<<BN_ / 8, 128, proj_smem>>>(h, Uw, Ub, Vw, Vb, Aw, Ab, Bw, Bb);
    fuse_mma_kernel<<<BN_, 128, fuse_smem>>>(e, Cw, Cb, e_out);
    finalize_stats_kernel<<<1, 128>>>(gamma_e, beta_e, gamma_h, beta_h);
    efinal_kernel<<<ESZ / 4 / 256, 256>>>(e, e_out);
    hfinal_kernel<<<HSZ / 4 / 256, 256>>>(h, h_out);
}

// round 4
// speedup vs baseline: 1.9863x; 1.5319x over previous
#include <cuda_runtime.h>
#include <cuda_bf16.h>
#include <cstdint>

#define B_ 8
#define N_ 200
#define D_ 128
#define BN_ (B_ * N_)            // 1600
#define HSZ (B_ * N_ * D_)       // 204800
#define ESZ (B_ * N_ * N_ * D_)  // 40960000
#define EPS 1e-5f

// ---------------- scratch (device globals, no allocation) ----------------
__device__ float g_Uh[HSZ];
__device__ float g_Vh[HSZ];
__device__ float g_Ah[HSZ];
__device__ float g_Bh[HSZ];
__device__ float g_hnew[HSZ];
__device__ float g_acc[4 * D_];   // e_sum, e_sqsum, h_sum, h_sqsum
__device__ float g_coef[4 * D_];  // scale_e, shift_e, scale_h, shift_h
__device__ uint32_t g_CwH[D_ * 64];  // bf16-pair-packed Cw hi, [d][kword]
__device__ uint32_t g_CwL[D_ * 64];  // bf16-pair-packed Cw lo, [d][kword]

// ---------------- K0: zero accumulators ----------------
__global__ void zero_acc_kernel() {
    int t = threadIdx.x;
    if (t < 4 * D_) g_acc[t] = 0.0f;
}

// ================= bf16 helpers ===========================================
__device__ __forceinline__ uint32_t pack_bf(float x, float y) {
    __nv_bfloat162 p = __floats2bfloat162_rn(x, y);
    return *reinterpret_cast<uint32_t*>(&p);
}

__device__ __forceinline__ void mma16816(float* c,
                                         uint32_t a0, uint32_t a1, uint32_t a2, uint32_t a3,
                                         uint32_t b0, uint32_t b1) {
    asm volatile(
        "mma.sync.aligned.m16n8k16.row.col.f32.bf16.bf16.f32 "
        "{%0,%1,%2,%3}, {%4,%5,%6,%7}, {%8,%9}, {%0,%1,%2,%3};"
        : "+f"(c[0]), "+f"(c[1]), "+f"(c[2]), "+f"(c[3])
        : "r"(a0), "r"(a1), "r"(a2), "r"(a3), "r"(b0), "r"(b1));
}

// ---------------- K0b: pack Cw -> bf16 hi/lo global (once per launch) -----
__global__ void cwpack_kernel(const float* __restrict__ Cw) {
    const int d = threadIdx.x;  // 128
    const float4* C4 = reinterpret_cast<const float4*>(Cw);
#pragma unroll 4
    for (int t = 0; t < 32; t++) {
        float4 v = C4[d * 32 + t];
        float hx = __bfloat162float(__float2bfloat16(v.x));
        float hy = __bfloat162float(__float2bfloat16(v.y));
        float hz = __bfloat162float(__float2bfloat16(v.z));
        float hw = __bfloat162float(__float2bfloat16(v.w));
        g_CwH[d * 64 + 2 * t + 0] = pack_bf(hx, hy);
        g_CwH[d * 64 + 2 * t + 1] = pack_bf(hz, hw);
        g_CwL[d * 64 + 2 * t + 0] = pack_bf(v.x - hx, v.y - hy);
        g_CwL[d * 64 + 2 * t + 1] = pack_bf(v.z - hz, v.w - hw);
    }
}

// ---------------- K1: four projections  Xh = h @ Xw^T + Xb ----------------
__global__ void proj_kernel(const float* __restrict__ h,
                            const float* __restrict__ Uw, const float* __restrict__ Ub,
                            const float* __restrict__ Vw, const float* __restrict__ Vb,
                            const float* __restrict__ Aw, const float* __restrict__ Ab,
                            const float* __restrict__ Bw, const float* __restrict__ Bb) {
    extern __shared__ float sm[];
    float* hs = sm;              // 8*128
    float* wt = sm + 1024;       // 128*129
    const int tid = threadIdx.x;
    const int row0 = blockIdx.x * 8;

#pragma unroll
    for (int r = 0; r < 8; r++) hs[r * D_ + tid] = h[(row0 + r) * D_ + tid];

    const float* Ws[4] = {Uw, Vw, Aw, Bw};
    const float* bs[4] = {Ub, Vb, Ab, Bb};
    float* outs[4] = {g_Uh, g_Vh, g_Ah, g_Bh};

    for (int m = 0; m < 4; m++) {
        __syncthreads();
        const float4* W4 = reinterpret_cast<const float4*>(Ws[m]);
#pragma unroll
        for (int t = 0; t < 32; t++) {
            int idx4 = t * 128 + tid;
            float4 v = W4[idx4];
            int d = idx4 >> 5;
            int k = (idx4 & 31) << 2;
            wt[(k + 0) * 129 + d] = v.x;
            wt[(k + 1) * 129 + d] = v.y;
            wt[(k + 2) * 129 + d] = v.z;
            wt[(k + 3) * 129 + d] = v.w;
        }
        __syncthreads();

        float acc[8] = {0, 0, 0, 0, 0, 0, 0, 0};
        for (int k = 0; k < D_; k++) {
            float w = wt[k * 129 + tid];
#pragma unroll
            for (int r = 0; r < 8; r++) acc[r] += hs[r * D_ + k] * w;
        }
        float bias = bs[m][tid];
#pragma unroll
        for (int r = 0; r < 8; r++)
            outs[m][(row0 + r) * D_ + tid] = acc[r] + bias;
    }
}

// smem word-layout constants for fuse
#define E_STRIDE 68     // words per j-row of e tiles (64 + 4 pad)
#define CWL_STRIDE 68   // words per d-row of Cw-lo tile
#define XS_STRIDE 132   // floats per j-row of x tile (128 + 4 pad)
#define CWL_OFF 0                       // 128*68 = 8704 words
#define EHI_OFF 8704                    // 64*68 = 4352
#define ELO_OFF (8704 + 4352)           // 13056
#define RED_OFF (8704 + 2 * 4352)       // 17408, 384 floats
#define FUSE_WORDS (17408 + 384)        // 17792 words = 71168 B

template <int NT>
__device__ __forceinline__ void mma_tile(const uint32_t* __restrict__ cwl,
                                         const uint32_t* __restrict__ e_hi,
                                         const uint32_t* __restrict__ e_lo,
                                         float acc[8][4],
                                         const uint32_t a_hi[8][4],
                                         int arow, int g, int tig) {
#pragma unroll
    for (int ks = 0; ks < 8; ks++) {
        uint32_t al0 = cwl[arow * CWL_STRIDE + 8 * ks + tig];
        uint32_t al1 = cwl[(arow + 8) * CWL_STRIDE + 8 * ks + tig];
        uint32_t al2 = cwl[arow * CWL_STRIDE + 8 * ks + tig + 4];
        uint32_t al3 = cwl[(arow + 8) * CWL_STRIDE + 8 * ks + tig + 4];
#pragma unroll
        for (int nt = 0; nt < NT; nt++) {
            int bofs = (8 * nt + g) * E_STRIDE + 8 * ks + tig;
            uint32_t bh0 = e_hi[bofs], bh1 = e_hi[bofs + 4];
            uint32_t bl0 = e_lo[bofs], bl1 = e_lo[bofs + 4];
            mma16816(acc[nt], a_hi[ks][0], a_hi[ks][1], a_hi[ks][2], a_hi[ks][3], bh0, bh1);
            mma16816(acc[nt], al0, al1, al2, al3, bh0, bh1);
            mma16816(acc[nt], a_hi[ks][0], a_hi[ks][1], a_hi[ks][2], a_hi[ks][3], bl0, bl1);
        }
    }
}

template <int NT>
__device__ __forceinline__ void spill_tile(float* __restrict__ XS, const float acc[8][4],
                                           int arow, int g, int tig) {
#pragma unroll
    for (int nt = 0; nt < NT; nt++) {
        const int jr = 8 * nt + 2 * tig;
        XS[jr * XS_STRIDE + arow] = acc[nt][0];
        XS[(jr + 1) * XS_STRIDE + arow] = acc[nt][1];
        XS[jr * XS_STRIDE + arow + 8] = acc[nt][2];
        XS[(jr + 1) * XS_STRIDE + arow + 8] = acc[nt][3];
    }
}

// ---------------- K2: mma.sync fused  Ce + e_new + gates + agg + stats ----
// grid = 1600 blocks (one per (b,i)), 256 threads (8 warps).
// Ce[d,j] = sum_k Cw[d,k] * e[bi,j,k]; A = Cw (hi in regs, lo in smem),
// B = e (hi/lo in smem). bf16x3 split (HH + LH + HL), fp32 accumulate.
__global__ void __launch_bounds__(256, 2)
fuse_mma_kernel(const float* __restrict__ e,
                const float* __restrict__ Cb,
                float* __restrict__ e_new_out) {
    extern __shared__ uint32_t smw[];
    uint32_t* cwl = smw + CWL_OFF;
    uint32_t* e_hi = smw + EHI_OFF;
    uint32_t* e_lo = smw + ELO_OFF;
    float* red = reinterpret_cast<float*>(smw + RED_OFF);
    float* XS = reinterpret_cast<float*>(smw + EHI_OFF);  // overlays e tiles

    const int tid = threadIdx.x;
    const int lane = tid & 31;
    const int warp = tid >> 5;     // 0..7
    const int g = lane >> 2;
    const int tig = lane & 3;
    const int arow = warp * 16 + g;
    const int bi = blockIdx.x;
    const int b = bi / N_;
    const int dcol = tid & 127;
    const int jh = tid >> 7;       // 0 or 1

    // zero smem reduction buffers
    if (tid < 128) {
        red[tid] = 0.0f;
        red[128 + tid] = 0.0f;
        red[256 + tid] = 0.0f;
    }

    // stage Cw-lo tile (plain copy from global pre-pack)
    for (int w = tid; w < D_ * 64; w += 256) {
        cwl[(w >> 6) * CWL_STRIDE + (w & 63)] = g_CwL[w];
    }

    // A-hi fragments: registers, loaded once
    uint32_t a_hi[8][4];
#pragma unroll
    for (int ks = 0; ks < 8; ks++) {
        a_hi[ks][0] = g_CwH[arow * 64 + 8 * ks + tig];
        a_hi[ks][1] = g_CwH[(arow + 8) * 64 + 8 * ks + tig];
        a_hi[ks][2] = g_CwH[arow * 64 + 8 * ks + tig + 4];
        a_hi[ks][3] = g_CwH[(arow + 8) * 64 + 8 * ks + tig + 4];
    }

    const float* e_base = e + (size_t)bi * N_ * D_;
    float* eo_base = e_new_out + (size_t)bi * N_ * D_;
    const float* Ah_b = g_Ah + (size_t)b * N_ * D_;
    const float* Vh_b = g_Vh + (size_t)b * N_ * D_;
    const float Bh_r = g_Bh[(size_t)bi * D_ + dcol];
    const float Cb_r = Cb[dcol];

    float sumv = 0.0f, sqv = 0.0f, aggv = 0.0f;

    for (int tile = 0; tile < 4; tile++) {
        const int j0 = tile * 64;
        const int jcnt = (tile < 3) ? 64 : (N_ - 192);   // 64,64,64,8

        // ---- stage e rows [j0, j0+jcnt) as bf16 hi/lo pairs ----
        {
            const float4* E4 = reinterpret_cast<const float4*>(e_base + (size_t)j0 * D_);
            const int nf4 = jcnt * 32;
            for (int fid = tid; fid < nf4; fid += 256) {
                int row = fid >> 5;
                int k4 = fid & 31;
                float4 v = E4[fid];
                float hx = __bfloat162float(__float2bfloat16(v.x));
                float hy = __bfloat162float(__float2bfloat16(v.y));
                float hz = __bfloat162float(__float2bfloat16(v.z));
                float hw = __bfloat162float(__float2bfloat16(v.w));
                int wofs = row * E_STRIDE + 2 * k4;
                *reinterpret_cast<uint2*>(&e_hi[wofs]) =
                    make_uint2(pack_bf(hx, hy), pack_bf(hz, hw));
                *reinterpret_cast<uint2*>(&e_lo[wofs]) =
                    make_uint2(pack_bf(v.x - hx, v.y - hy), pack_bf(v.z - hz, v.w - hw));
            }
        }
        __syncthreads();

        // ---- mma + spill ----
        float acc[8][4];
#pragma unroll
        for (int nt = 0; nt < 8; nt++)
#pragma unroll
            for (int q = 0; q < 4; q++) acc[nt][q] = 0.0f;

        if (tile < 3) {
            mma_tile<8>(cwl, e_hi, e_lo, acc, a_hi, arow, g, tig);
        } else {
            mma_tile<1>(cwl, e_hi, e_lo, acc, a_hi, arow, g, tig);
        }
        __syncthreads();   // all reads of e tiles done before XS overlay

        if (tile < 3) {
            spill_tile<8>(XS, acc, arow, g, tig);
        } else {
            spill_tile<1>(XS, acc, arow, g, tig);
        }
        __syncthreads();

        // ---- column pass: thread (dcol, jh) ----
        const int half = jcnt >> 1;
        for (int jj = 0; jj < half; jj++) {
            const int j = jh * half + jj;
            float x = XS[j * XS_STRIDE + dcol] + Cb_r + Bh_r + Ah_b[(j0 + j) * D_ + dcol];
            eo_base[(size_t)(j0 + j) * D_ + dcol] = x;
            sumv += x;
            sqv += x * x;
            float gte = __fdividef(1.0f, 1.0f + __expf(-x));
            aggv += gte * Vh_b[(j0 + j) * D_ + dcol];
        }
        __syncthreads();   // column pass done before next staging overwrites
    }

    // ---- merge the two j-halves, then one global update per d ----
    atomicAdd(&red[dcol], aggv);
    atomicAdd(&red[128 + dcol], sumv);
    atomicAdd(&red[256 + dcol], sqv);
    __syncthreads();

    if (tid < 128) {
        const int d = tid;
        float hn = g_Uh[(size_t)bi * D_ + d] + red[d];
        g_hnew[(size_t)bi * D_ + d] = hn;
        atomicAdd(&g_acc[0 * D_ + d], red[128 + d]);
        atomicAdd(&g_acc[1 * D_ + d], red[256 + d]);
        atomicAdd(&g_acc[2 * D_ + d], hn);
        atomicAdd(&g_acc[3 * D_ + d], hn * hn);
    }
}

// ---------------- K3: BN stats -> scale/shift -----------------------------
__global__ void finalize_stats_kernel(const float* __restrict__ gamma_e,
                                      const float* __restrict__ beta_e,
                                      const float* __restrict__ gamma_h,
                                      const float* __restrict__ beta_h) {
    int d = threadIdx.x;
    const float Ne = (float)B_ * N_ * N_;
    float mu = g_acc[d] / Ne;
    float var = g_acc[D_ + d] / Ne - mu * mu;
    float sc = rsqrtf(var + EPS) * gamma_e[d];
    g_coef[d] = sc;
    g_coef[D_ + d] = beta_e[d] - mu * sc;

    const float Nh = (float)B_ * N_;
    float muh = g_acc[2 * D_ + d] / Nh;
    float varh = g_acc[3 * D_ + d] / Nh - muh * muh;
    float sch = rsqrtf(varh + EPS) * gamma_h[d];
    g_coef[2 * D_ + d] = sch;
    g_coef[3 * D_ + d] = beta_h[d] - muh * sch;
}

// ---------------- K4: e epilogue (in-place over e_new region) -------------
__global__ void efinal_kernel(const float* __restrict__ e_in, float* __restrict__ e_out) {
    size_t idx = (size_t)blockIdx.x * blockDim.x + threadIdx.x;
    int d4 = (int)(idx & 31);
    float4 sc = reinterpret_cast<const float4*>(g_coef)[d4];
    float4 sh = reinterpret_cast<const float4*>(g_coef + D_)[d4];
    float4 x = reinterpret_cast<const float4*>(e_out)[idx];
    float4 ei = reinterpret_cast<const float4*>(e_in)[idx];
    float4 r;
    r.x = ei.x + fmaxf(0.0f, x.x * sc.x + sh.x);
    r.y = ei.y + fmaxf(0.0f, x.y * sc.y + sh.y);
    r.z = ei.z + fmaxf(0.0f, x.z * sc.z + sh.z);
    r.w = ei.w + fmaxf(0.0f, x.w * sc.w + sh.w);
    reinterpret_cast<float4*>(e_out)[idx] = r;
}

// ---------------- K5: h epilogue ------------------------------------------
__global__ void hfinal_kernel(const float* __restrict__ h_in, float* __restrict__ h_out) {
    size_t idx = (size_t)blockIdx.x * blockDim.x + threadIdx.x;
    int d4 = (int)(idx & 31);
    float4 sc = reinterpret_cast<const float4*>(g_coef + 2 * D_)[d4];
    float4 sh = reinterpret_cast<const float4*>(g_coef + 3 * D_)[d4];
    float4 x = reinterpret_cast<const float4*>(g_hnew)[idx];
    float4 hi = reinterpret_cast<const float4*>(h_in)[idx];
    float4 r;
    r.x = hi.x + fmaxf(0.0f, x.x * sc.x + sh.x);
    r.y = hi.y + fmaxf(0.0f, x.y * sc.y + sh.y);
    r.z = hi.z + fmaxf(0.0f, x.z * sc.z + sh.z);
    r.w = hi.w + fmaxf(0.0f, x.w * sc.w + sh.w);
    reinterpret_cast<float4*>(h_out)[idx] = r;
}

// ---------------- launch ---------------------------------------------------
extern "C" void kernel_launch(void* const* d_in, const int* in_sizes, int n_in,
                              void* d_out, int out_size) {
    const float* h = (const float*)d_in[0];
    const float* e = (const float*)d_in[1];
    const float* Uw = (const float*)d_in[2];
    const float* Ub = (const float*)d_in[3];
    const float* Vw = (const float*)d_in[4];
    const float* Vb = (const float*)d_in[5];
    const float* Aw = (const float*)d_in[6];
    const float* Ab = (const float*)d_in[7];
    const float* Bw = (const float*)d_in[8];
    const float* Bb = (const float*)d_in[9];
    const float* Cw = (const float*)d_in[10];
    const float* Cb = (const float*)d_in[11];
    const float* gamma_h = (const float*)d_in[12];
    const float* beta_h = (const float*)d_in[13];
    const float* gamma_e = (const float*)d_in[14];
    const float* beta_e = (const float*)d_in[15];

    float* out = (float*)d_out;
    float* h_out = out;          // [B,N,D]
    float* e_out = out + HSZ;    // [B,N,N,D] (e_new scratch then final)

    static int attr_done = 0;
    const int proj_smem = (1024 + 16512) * 4;   // 70144 B
    const int fuse_smem = FUSE_WORDS * 4;       // 71168 B
    if (!attr_done) {
        cudaFuncSetAttribute(proj_kernel, cudaFuncAttributeMaxDynamicSharedMemorySize, proj_smem);
        cudaFuncSetAttribute(fuse_mma_kernel, cudaFuncAttributeMaxDynamicSharedMemorySize, fuse_smem);
        attr_done = 1;
    }

    zero_acc_kernel<<<1, 512>>>();
    cwpack_kernel<<<1, 128>>>(Cw);
    proj_kernel<<<BN_ / 8, 128, proj_smem>>>(h, Uw, Ub, Vw, Vb, Aw, Ab, Bw, Bb);
    fuse_mma_kernel<<<BN_, 256, fuse_smem>>>(e, Cb, e_out);
    finalize_stats_kernel<<<1, 128>>>(gamma_e, beta_e, gamma_h, beta_h);
    efinal_kernel<<<ESZ / 4 / 256, 256>>>(e, e_out);
    hfinal_kernel<<<HSZ / 4 / 256, 256>>>(h, h_out);
}

// round 5
// speedup vs baseline: 2.7473x; 1.3831x over previous
#include <cuda_runtime.h>
#include <cuda_bf16.h>
#include <cstdint>

#define B_ 8
#define N_ 200
#define D_ 128
#define BN_ (B_ * N_)            // 1600
#define HSZ (B_ * N_ * D_)       // 204800
#define ESZ (B_ * N_ * N_ * D_)  // 40960000
#define EPS 1e-5f

// ---------------- scratch (device globals, no allocation) ----------------
__device__ float g_Uh[HSZ];
__device__ float g_Vh[HSZ];
__device__ float g_Ah[HSZ];
__device__ float g_Bh[HSZ];
__device__ float g_hnew[HSZ];
__device__ float g_acc[4 * D_];   // e_sum, e_sqsum, h_sum, h_sqsum
__device__ float g_coef[4 * D_];  // scale_e, shift_e, scale_h, shift_h
__device__ uint32_t g_CwH[D_ * 64];  // bf16-pair-packed Cw hi, [d][kword]
__device__ uint32_t g_CwL[D_ * 64];  // bf16-pair-packed Cw lo, [d][kword]

// ---------------- K0: zero accumulators ----------------
__global__ void zero_acc_kernel() {
    int t = threadIdx.x;
    if (t < 4 * D_) g_acc[t] = 0.0f;
}

// ================= helpers ===========================================
__device__ __forceinline__ uint32_t pack_bf(float x, float y) {
    __nv_bfloat162 p = __floats2bfloat162_rn(x, y);
    return *reinterpret_cast<uint32_t*>(&p);
}

__device__ __forceinline__ void mma16816(float* c,
                                         uint32_t a0, uint32_t a1, uint32_t a2, uint32_t a3,
                                         uint32_t b0, uint32_t b1) {
    asm volatile(
        "mma.sync.aligned.m16n8k16.row.col.f32.bf16.bf16.f32 "
        "{%0,%1,%2,%3}, {%4,%5,%6,%7}, {%8,%9}, {%0,%1,%2,%3};"
        : "+f"(c[0]), "+f"(c[1]), "+f"(c[2]), "+f"(c[3])
        : "r"(a0), "r"(a1), "r"(a2), "r"(a3), "r"(b0), "r"(b1));
}

__device__ __forceinline__ uint32_t smem_u32(const void* p) {
    uint32_t a;
    asm("{ .reg .u64 t; cvta.to.shared.u64 t, %1; cvt.u32.u64 %0, t; }" : "=r"(a) : "l"(p));
    return a;
}
#define CP_ASYNC16(dst, src) \
    asm volatile("cp.async.cg.shared.global [%0], [%1], 16;" :: "r"(dst), "l"(src))
#define CP_COMMIT() asm volatile("cp.async.commit_group;" ::: "memory")
#define CP_WAIT0() asm volatile("cp.async.wait_group 0;" ::: "memory")

// ---------------- K0b: pack Cw -> bf16 hi/lo global (once per launch) -----
__global__ void cwpack_kernel(const float* __restrict__ Cw) {
    const int d = threadIdx.x;  // 128
    const float4* C4 = reinterpret_cast<const float4*>(Cw);
#pragma unroll 4
    for (int t = 0; t < 32; t++) {
        float4 v = C4[d * 32 + t];
        float hx = __bfloat162float(__float2bfloat16(v.x));
        float hy = __bfloat162float(__float2bfloat16(v.y));
        float hz = __bfloat162float(__float2bfloat16(v.z));
        float hw = __bfloat162float(__float2bfloat16(v.w));
        g_CwH[d * 64 + 2 * t + 0] = pack_bf(hx, hy);
        g_CwH[d * 64 + 2 * t + 1] = pack_bf(hz, hw);
        g_CwL[d * 64 + 2 * t + 0] = pack_bf(v.x - hx, v.y - hy);
        g_CwL[d * 64 + 2 * t + 1] = pack_bf(v.z - hz, v.w - hw);
    }
}

// ---------------- K1: four projections  Xh = h @ Xw^T + Xb ----------------
__global__ void proj_kernel(const float* __restrict__ h,
                            const float* __restrict__ Uw, const float* __restrict__ Ub,
                            const float* __restrict__ Vw, const float* __restrict__ Vb,
                            const float* __restrict__ Aw, const float* __restrict__ Ab,
                            const float* __restrict__ Bw, const float* __restrict__ Bb) {
    extern __shared__ float sm[];
    float* hs = sm;              // 8*128
    float* wt = sm + 1024;       // 128*129
    const int tid = threadIdx.x;
    const int row0 = blockIdx.x * 8;

#pragma unroll
    for (int r = 0; r < 8; r++) hs[r * D_ + tid] = h[(row0 + r) * D_ + tid];

    const float* Ws[4] = {Uw, Vw, Aw, Bw};
    const float* bs[4] = {Ub, Vb, Ab, Bb};
    float* outs[4] = {g_Uh, g_Vh, g_Ah, g_Bh};

    for (int m = 0; m < 4; m++) {
        __syncthreads();
        const float4* W4 = reinterpret_cast<const float4*>(Ws[m]);
#pragma unroll
        for (int t = 0; t < 32; t++) {
            int idx4 = t * 128 + tid;
            float4 v = W4[idx4];
            int d = idx4 >> 5;
            int k = (idx4 & 31) << 2;
            wt[(k + 0) * 129 + d] = v.x;
            wt[(k + 1) * 129 + d] = v.y;
            wt[(k + 2) * 129 + d] = v.z;
            wt[(k + 3) * 129 + d] = v.w;
        }
        __syncthreads();

        float acc[8] = {0, 0, 0, 0, 0, 0, 0, 0};
        for (int k = 0; k < D_; k++) {
            float w = wt[k * 129 + tid];
#pragma unroll
            for (int r = 0; r < 8; r++) acc[r] += hs[r * D_ + k] * w;
        }
        float bias = bs[m][tid];
#pragma unroll
        for (int r = 0; r < 8; r++)
            outs[m][(row0 + r) * D_ + tid] = acc[r] + bias;
    }
}

// smem word-layout constants for fuse
#define E_STRIDE 68     // words per j-row of e tiles (64 + 4 pad)
#define CWL_STRIDE 68   // words per d-row of Cw-lo tile
#define XS_STRIDE 132   // floats per j-row of x tile (128 + 4 pad)
#define CWL_OFF 0                        // 128*68 = 8704 words
#define RAW_OFF 8704                     // 64*128 = 8192 words (raw fp32 e tile)
#define EHI_OFF (8704 + 8192)            // 16896; 64*68 = 4352 words
#define ELO_OFF (16896 + 4352)           // 21248
#define RED_OFF (16896 + 2 * 4352)       // 25600, 384 floats
#define FUSE_WORDS (25600 + 384)         // 25984 words = 103936 B
// XS (64*132 = 8448 floats) overlays EHI..ELO region (8704 words)

template <int NT>
__device__ __forceinline__ void mma_tile(const uint32_t* __restrict__ cwl,
                                         const uint32_t* __restrict__ e_hi,
                                         const uint32_t* __restrict__ e_lo,
                                         float acc[8][4],
                                         const uint32_t a_hi[8][4],
                                         int arow, int g, int tig) {
#pragma unroll
    for (int ks = 0; ks < 8; ks++) {
        uint32_t al0 = cwl[arow * CWL_STRIDE + 8 * ks + tig];
        uint32_t al1 = cwl[(arow + 8) * CWL_STRIDE + 8 * ks + tig];
        uint32_t al2 = cwl[arow * CWL_STRIDE + 8 * ks + tig + 4];
        uint32_t al3 = cwl[(arow + 8) * CWL_STRIDE + 8 * ks + tig + 4];
#pragma unroll
        for (int nt = 0; nt < NT; nt++) {
            int bofs = (8 * nt + g) * E_STRIDE + 8 * ks + tig;
            uint32_t bh0 = e_hi[bofs], bh1 = e_hi[bofs + 4];
            uint32_t bl0 = e_lo[bofs], bl1 = e_lo[bofs + 4];
            mma16816(acc[nt], a_hi[ks][0], a_hi[ks][1], a_hi[ks][2], a_hi[ks][3], bh0, bh1);
            mma16816(acc[nt], al0, al1, al2, al3, bh0, bh1);
            mma16816(acc[nt], a_hi[ks][0], a_hi[ks][1], a_hi[ks][2], a_hi[ks][3], bl0, bl1);
        }
    }
}

template <int NT>
__device__ __forceinline__ void spill_tile(float* __restrict__ XS, const float acc[8][4],
                                           int arow, int g, int tig) {
#pragma unroll
    for (int nt = 0; nt < NT; nt++) {
        const int jr = 8 * nt + 2 * tig;
        XS[jr * XS_STRIDE + arow] = acc[nt][0];
        XS[(jr + 1) * XS_STRIDE + arow] = acc[nt][1];
        XS[jr * XS_STRIDE + arow + 8] = acc[nt][2];
        XS[(jr + 1) * XS_STRIDE + arow + 8] = acc[nt][3];
    }
}

// ---------------- K2: mma.sync fused, cp.async pipelined ------------------
// grid = 1600 blocks (one per (b,i)), 256 threads (8 warps).
// Ce[d,j] = sum_k Cw[d,k] * e[bi,j,k]; A = Cw (hi regs, lo smem), B = e smem.
// bf16x3 split (HH + LH + HL), fp32 accumulate.
__global__ void __launch_bounds__(256, 2)
fuse_mma_kernel(const float* __restrict__ e,
                const float* __restrict__ Cb,
                float* __restrict__ e_new_out) {
    extern __shared__ uint32_t smw[];
    uint32_t* cwl = smw + CWL_OFF;
    float* raw = reinterpret_cast<float*>(smw + RAW_OFF);
    uint32_t* e_hi = smw + EHI_OFF;
    uint32_t* e_lo = smw + ELO_OFF;
    float* red = reinterpret_cast<float*>(smw + RED_OFF);
    float* XS = reinterpret_cast<float*>(smw + EHI_OFF);  // overlays e tiles

    const int tid = threadIdx.x;
    const int lane = tid & 31;
    const int warp = tid >> 5;     // 0..7
    const int g = lane >> 2;
    const int tig = lane & 3;
    const int arow = warp * 16 + g;
    const int bi = blockIdx.x;
    const int b = bi / N_;
    const int dcol = tid & 127;
    const int jh = tid >> 7;       // 0 or 1

    const float* e_base = e + (size_t)bi * N_ * D_;
    const uint32_t raw_s = smem_u32(raw);

    // ---- prologue: async-stage raw tile 0, then do setup work ----
    {
        const float4* E4 = reinterpret_cast<const float4*>(e_base);
#pragma unroll
        for (int u = 0; u < 8; u++) {
            int fid = tid + u * 256;           // 2048 float4 = 64 rows
            CP_ASYNC16(raw_s + fid * 16, (const char*)(E4 + fid));
        }
        CP_COMMIT();
    }

    if (tid < 128) {
        red[tid] = 0.0f;
        red[128 + tid] = 0.0f;
        red[256 + tid] = 0.0f;
    }
    // stage Cw-lo tile
    for (int w = tid; w < D_ * 64; w += 256) {
        cwl[(w >> 6) * CWL_STRIDE + (w & 63)] = g_CwL[w];
    }
    // A-hi fragments in registers
    uint32_t a_hi[8][4];
#pragma unroll
    for (int ks = 0; ks < 8; ks++) {
        a_hi[ks][0] = g_CwH[arow * 64 + 8 * ks + tig];
        a_hi[ks][1] = g_CwH[(arow + 8) * 64 + 8 * ks + tig];
        a_hi[ks][2] = g_CwH[arow * 64 + 8 * ks + tig + 4];
        a_hi[ks][3] = g_CwH[(arow + 8) * 64 + 8 * ks + tig + 4];
    }

    float* eo_base = e_new_out + (size_t)bi * N_ * D_;
    const float* Ah_b = g_Ah + (size_t)b * N_ * D_;
    const float* Vh_b = g_Vh + (size_t)b * N_ * D_;
    const float Bh_r = g_Bh[(size_t)bi * D_ + dcol];
    const float Cb_r = Cb[dcol];

    float sumv = 0.0f, sqv = 0.0f, aggv = 0.0f;

    CP_WAIT0();
    __syncthreads();   // raw(0) ready; cwl ready

    for (int tile = 0; tile < 4; tile++) {
        const int j0 = tile * 64;
        const int jcnt = (tile < 3) ? 64 : (N_ - 192);   // 64,64,64,8

        // ---- convert raw -> bf16 hi/lo pairs (smem -> smem) ----
        {
            const int nf4 = jcnt * 32;
            for (int fid = tid; fid < nf4; fid += 256) {
                int row = fid >> 5;
                int k4 = fid & 31;
                float4 v = *reinterpret_cast<const float4*>(&raw[fid * 4]);
                float hx = __bfloat162float(__float2bfloat16(v.x));
                float hy = __bfloat162float(__float2bfloat16(v.y));
                float hz = __bfloat162float(__float2bfloat16(v.z));
                float hw = __bfloat162float(__float2bfloat16(v.w));
                int wofs = row * E_STRIDE + 2 * k4;
                *reinterpret_cast<uint2*>(&e_hi[wofs]) =
                    make_uint2(pack_bf(hx, hy), pack_bf(hz, hw));
                *reinterpret_cast<uint2*>(&e_lo[wofs]) =
                    make_uint2(pack_bf(v.x - hx, v.y - hy), pack_bf(v.z - hz, v.w - hw));
            }
        }
        __syncthreads();   // e tiles ready; raw buffer free

        // ---- async-stage next raw tile (latency hidden by mma+column) ----
        if (tile < 3) {
            const int njcnt = (tile < 2) ? 64 : (N_ - 192);
            const int nnf4 = njcnt * 32;
            const float4* E4 = reinterpret_cast<const float4*>(e_base + (size_t)(j0 + 64) * D_);
            for (int fid = tid; fid < nnf4; fid += 256) {
                CP_ASYNC16(raw_s + fid * 16, (const char*)(E4 + fid));
            }
            CP_COMMIT();
        }

        // ---- mma ----
        float acc[8][4];
#pragma unroll
        for (int nt = 0; nt < 8; nt++)
#pragma unroll
            for (int q = 0; q < 4; q++) acc[nt][q] = 0.0f;

        if (tile < 3) {
            mma_tile<8>(cwl, e_hi, e_lo, acc, a_hi, arow, g, tig);
        } else {
            mma_tile<1>(cwl, e_hi, e_lo, acc, a_hi, arow, g, tig);
        }
        __syncthreads();   // all mma reads of e tiles done before XS overlay

        if (tile < 3) {
            spill_tile<8>(XS, acc, arow, g, tig);
        } else {
            spill_tile<1>(XS, acc, arow, g, tig);
        }
        __syncthreads();

        // ---- column pass: thread (dcol, jh), batched prefetch ----
        const int half = jcnt >> 1;
        if (half == 32) {
#pragma unroll
            for (int jj0 = 0; jj0 < 32; jj0 += 8) {
                float xv[8], av[8], vv[8];
#pragma unroll
                for (int u = 0; u < 8; u++) {
                    const int j = jh * 32 + jj0 + u;
                    xv[u] = XS[j * XS_STRIDE + dcol];
                    av[u] = Ah_b[(j0 + j) * D_ + dcol];
                    vv[u] = Vh_b[(j0 + j) * D_ + dcol];
                }
#pragma unroll
                for (int u = 0; u < 8; u++) {
                    const int j = jh * 32 + jj0 + u;
                    float x = xv[u] + Cb_r + Bh_r + av[u];
                    eo_base[(size_t)(j0 + j) * D_ + dcol] = x;
                    sumv += x;
                    sqv += x * x;
                    float gte = __fdividef(1.0f, 1.0f + __expf(-x));
                    aggv += gte * vv[u];
                }
            }
        } else {
            for (int jj = 0; jj < half; jj++) {
                const int j = jh * half + jj;
                float x = XS[j * XS_STRIDE + dcol] + Cb_r + Bh_r + Ah_b[(j0 + j) * D_ + dcol];
                eo_base[(size_t)(j0 + j) * D_ + dcol] = x;
                sumv += x;
                sqv += x * x;
                float gte = __fdividef(1.0f, 1.0f + __expf(-x));
                aggv += gte * Vh_b[(j0 + j) * D_ + dcol];
            }
        }
        CP_WAIT0();
        __syncthreads();   // XS free + raw(t+1) arrived
    }

    // ---- merge the two j-halves, then one global update per d ----
    atomicAdd(&red[dcol], aggv);
    atomicAdd(&red[128 + dcol], sumv);
    atomicAdd(&red[256 + dcol], sqv);
    __syncthreads();

    if (tid < 128) {
        const int d = tid;
        float hn = g_Uh[(size_t)bi * D_ + d] + red[d];
        g_hnew[(size_t)bi * D_ + d] = hn;
        atomicAdd(&g_acc[0 * D_ + d], red[128 + d]);
        atomicAdd(&g_acc[1 * D_ + d], red[256 + d]);
        atomicAdd(&g_acc[2 * D_ + d], hn);
        atomicAdd(&g_acc[3 * D_ + d], hn * hn);
    }
}

// ---------------- K3: BN stats -> scale/shift -----------------------------
__global__ void finalize_stats_kernel(const float* __restrict__ gamma_e,
                                      const float* __restrict__ beta_e,
                                      const float* __restrict__ gamma_h,
                                      const float* __restrict__ beta_h) {
    int d = threadIdx.x;
    const float Ne = (float)B_ * N_ * N_;
    float mu = g_acc[d] / Ne;
    float var = g_acc[D_ + d] / Ne - mu * mu;
    float sc = rsqrtf(var + EPS) * gamma_e[d];
    g_coef[d] = sc;
    g_coef[D_ + d] = beta_e[d] - mu * sc;

    const float Nh = (float)B_ * N_;
    float muh = g_acc[2 * D_ + d] / Nh;
    float varh = g_acc[3 * D_ + d] / Nh - muh * muh;
    float sch = rsqrtf(varh + EPS) * gamma_h[d];
    g_coef[2 * D_ + d] = sch;
    g_coef[3 * D_ + d] = beta_h[d] - muh * sch;
}

// ---------------- K4: e epilogue (in-place over e_new region) -------------
__global__ void efinal_kernel(const float* __restrict__ e_in, float* __restrict__ e_out) {
    size_t idx = (size_t)blockIdx.x * blockDim.x + threadIdx.x;
    int d4 = (int)(idx & 31);
    float4 sc = reinterpret_cast<const float4*>(g_coef)[d4];
    float4 sh = reinterpret_cast<const float4*>(g_coef + D_)[d4];
    float4 x = reinterpret_cast<const float4*>(e_out)[idx];
    float4 ei = reinterpret_cast<const float4*>(e_in)[idx];
    float4 r;
    r.x = ei.x + fmaxf(0.0f, x.x * sc.x + sh.x);
    r.y = ei.y + fmaxf(0.0f, x.y * sc.y + sh.y);
    r.z = ei.z + fmaxf(0.0f, x.z * sc.z + sh.z);
    r.w = ei.w + fmaxf(0.0f, x.w * sc.w + sh.w);
    reinterpret_cast<float4*>(e_out)[idx] = r;
}

// ---------------- K5: h epilogue ------------------------------------------
__global__ void hfinal_kernel(const float* __restrict__ h_in, float* __restrict__ h_out) {
    size_t idx = (size_t)blockIdx.x * blockDim.x + threadIdx.x;
    int d4 = (int)(idx & 31);
    float4 sc = reinterpret_cast<const float4*>(g_coef + 2 * D_)[d4];
    float4 sh = reinterpret_cast<const float4*>(g_coef + 3 * D_)[d4];
    float4 x = reinterpret_cast<const float4*>(g_hnew)[idx];
    float4 hi = reinterpret_cast<const float4*>(h_in)[idx];
    float4 r;
    r.x = hi.x + fmaxf(0.0f, x.x * sc.x + sh.x);
    r.y = hi.y + fmaxf(0.0f, x.y * sc.y + sh.y);
    r.z = hi.z + fmaxf(0.0f, x.z * sc.z + sh.z);
    r.w = hi.w + fmaxf(0.0f, x.w * sc.w + sh.w);
    reinterpret_cast<float4*>(h_out)[idx] = r;
}

// ---------------- launch ---------------------------------------------------
extern "C" void kernel_launch(void* const* d_in, const int* in_sizes, int n_in,
                              void* d_out, int out_size) {
    const float* h = (const float*)d_in[0];
    const float* e = (const float*)d_in[1];
    const float* Uw = (const float*)d_in[2];
    const float* Ub = (const float*)d_in[3];
    const float* Vw = (const float*)d_in[4];
    const float* Vb = (const float*)d_in[5];
    const float* Aw = (const float*)d_in[6];
    const float* Ab = (const float*)d_in[7];
    const float* Bw = (const float*)d_in[8];
    const float* Bb = (const float*)d_in[9];
    const float* Cw = (const float*)d_in[10];
    const float* Cb = (const float*)d_in[11];
    const float* gamma_h = (const float*)d_in[12];
    const float* beta_h = (const float*)d_in[13];
    const float* gamma_e = (const float*)d_in[14];
    const float* beta_e = (const float*)d_in[15];

    float* out = (float*)d_out;
    float* h_out = out;          // [B,N,D]
    float* e_out = out + HSZ;    // [B,N,N,D] (e_new scratch then final)

    static int attr_done = 0;
    const int proj_smem = (1024 + 16512) * 4;   // 70144 B
    const int fuse_smem = FUSE_WORDS * 4;       // 103936 B
    if (!attr_done) {
        cudaFuncSetAttribute(proj_kernel, cudaFuncAttributeMaxDynamicSharedMemorySize, proj_smem);
        cudaFuncSetAttribute(fuse_mma_kernel, cudaFuncAttributeMaxDynamicSharedMemorySize, fuse_smem);
        attr_done = 1;
    }

    zero_acc_kernel<<<1, 512>>>();
    cwpack_kernel<<<1, 128>>>(Cw);
    proj_kernel<<<BN_ / 8, 128, proj_smem>>>(h, Uw, Ub, Vw, Vb, Aw, Ab, Bw, Bb);
    fuse_mma_kernel<<<BN_, 256, fuse_smem>>>(e, Cb, e_out);
    finalize_stats_kernel<<<1, 128>>>(gamma_e, beta_e, gamma_h, beta_h);
    efinal_kernel<<<ESZ / 4 / 256, 256>>>(e, e_out);
    hfinal_kernel<<<HSZ / 4 / 256, 256>>>(h, h_out);
}